// round 1
// baseline (speedup 1.0000x reference)
#include <cuda_runtime.h>
#include <cuda_bf16.h>
#include <math.h>

typedef unsigned long long ull;

#define B_ROWS 4096
#define IN_F   1024
#define LW     64
#define OUT_F  512
#define NLEAF  64
#define HCOLS  4096          /* NLEAF*LW */
#define HLD    4160          /* HCOLS + NLEAF mixture tail, K of GEMM2 */

// Scratch (static device globals; no runtime allocation allowed)
__device__ float g_H[(size_t)B_ROWS * HLD];     // [4096, 4160]
__device__ float g_mix[B_ROWS * NLEAF];         // [4096, 64]

// ---------- packed f32x2 helpers (FFMA2 path: 128 fp32 MACs/cyc/SM) ----------
__device__ __forceinline__ ull pack2_dup(float x) {
    ull r; asm("mov.b64 %0, {%1, %1};" : "=l"(r) : "f"(x)); return r;
}
__device__ __forceinline__ ull fma2(ull a, ull b, ull c) {
    ull d; asm("fma.rn.f32x2 %0, %1, %2, %3;" : "=l"(d) : "l"(a), "l"(b), "l"(c)); return d;
}
__device__ __forceinline__ void unpack2(ull v, float &lo, float &hi) {
    asm("mov.b64 {%0, %1}, %2;" : "=f"(lo), "=f"(hi) : "l"(v));
}

// =====================================================================
// Kernel 1: routing tree -> mixture[4096, 64]; also writes mixture into
// the tail columns [4096..4159] of g_H so GEMM2 folds the b2s bias term.
// =====================================================================
__global__ __launch_bounds__(256) void mix_kernel(
    const float* __restrict__ x,       // [4096, 1024]
    const float* __restrict__ nw,      // [63, 1024]
    const float* __restrict__ nb)      // [63]
{
    __shared__ float xs[IN_F];
    __shared__ float lg[64];

    const int b   = blockIdx.x;
    const int tid = threadIdx.x;

    // load x row (256 * float4 = 1024 floats)
    ((float4*)xs)[tid] = ((const float4*)(x + (size_t)b * IN_F))[tid];
    __syncthreads();

    const int warp = tid >> 5, lane = tid & 31;
    for (int n = warp; n < 63; n += 8) {
        const float* w = nw + (size_t)n * IN_F;
        float s0 = 0.f, s1 = 0.f, s2 = 0.f, s3 = 0.f;
#pragma unroll
        for (int j = 0; j < 8; ++j) {
            int o = lane + 128 * j;
            s0 += xs[o      ] * w[o      ];
            s1 += xs[o + 32 ] * w[o + 32 ];
            s2 += xs[o + 64 ] * w[o + 64 ];
            s3 += xs[o + 96 ] * w[o + 96 ];
        }
        float s = (s0 + s1) + (s2 + s3);
#pragma unroll
        for (int o = 16; o > 0; o >>= 1) s += __shfl_xor_sync(0xffffffffu, s, o);
        if (lane == 0) lg[n] = s + nb[n];
    }
    __syncthreads();

    if (tid < 64) {
        const int l = tid;
        float m = 1.f;
#pragma unroll
        for (int d = 0; d < 6; ++d) {
            int idx = (1 << d) - 1 + (l >> (6 - d));   // ancestor node at depth d
            float sg = 1.f / (1.f + expf(-lg[idx]));
            m *= ((l >> (5 - d)) & 1) ? sg : (1.f - sg);
        }
        g_mix[b * NLEAF + l] = m;
        g_H[(size_t)b * HLD + HCOLS + l] = m;          // bias-fold tail column
    }
}

// =====================================================================
// Kernel 2: H[:, 0:4096] = relu(x @ W1cat + b1) * mix   (M=4096,N=4096,K=1024)
// 128x128x16 tiles, 256 threads, 8x8 outputs/thread via f32x2 pairs along N.
// =====================================================================
__global__ __launch_bounds__(256) void gemm1_kernel(
    const float* __restrict__ X,       // [4096, 1024]
    const float* __restrict__ W1,      // [64, 1024, 64]
    const float* __restrict__ B1)      // [64*64] flat == column index
{
    __shared__ float As[2][16][128];   // As[k][m]
    __shared__ float Bs[2][16][128];   // Bs[k][n]

    const int tid = threadIdx.x;
    const int bn = blockIdx.x, bm = blockIdx.y;
    const int tx = tid & 15, ty = tid >> 4;
    const int row0 = bm * 128, col0 = bn * 128;

    // A-load mapping: q in {0,1}: row = tid/4 (+64), k4 = (tid%4)*4
    const int rA = tid >> 2, cA = (tid & 3) * 4;
    // B-load mapping: q in {0,1}: k = tid/32 (+8), n = (tid%32)*4
    const int kB = tid >> 5, nB = (tid & 31) * 4;
    const int leafB = (col0 + nB) >> 6;
    const int wB    = (col0 + nB) & 63;

    const float* A0 = X + (size_t)(row0 + rA) * IN_F + cA;
    const float* A1 = A0 + (size_t)64 * IN_F;
    const float* Bb0 = W1 + ((size_t)leafB * IN_F + kB) * 64 + wB;
    const float* Bb1 = Bb0 + (size_t)8 * 64;

    ull acc[8][4];
#pragma unroll
    for (int i = 0; i < 8; ++i)
#pragma unroll
        for (int j = 0; j < 4; ++j) acc[i][j] = 0ull;

    float4 ra0, ra1, rb0, rb1;

    // prologue: tile 0
    ra0 = *(const float4*)(A0);
    ra1 = *(const float4*)(A1);
    rb0 = *(const float4*)(Bb0);
    rb1 = *(const float4*)(Bb1);
    As[0][cA + 0][rA] = ra0.x; As[0][cA + 1][rA] = ra0.y;
    As[0][cA + 2][rA] = ra0.z; As[0][cA + 3][rA] = ra0.w;
    As[0][cA + 0][rA + 64] = ra1.x; As[0][cA + 1][rA + 64] = ra1.y;
    As[0][cA + 2][rA + 64] = ra1.z; As[0][cA + 3][rA + 64] = ra1.w;
    *(float4*)&Bs[0][kB    ][nB] = rb0;
    *(float4*)&Bs[0][kB + 8][nB] = rb1;
    __syncthreads();

    const int NT = IN_F / 16;  // 64
    for (int kt = 0; kt < NT; ++kt) {
        const int cur = kt & 1, nxt = cur ^ 1;
        if (kt + 1 < NT) {
            ra0 = *(const float4*)(A0 + (kt + 1) * 16);
            ra1 = *(const float4*)(A1 + (kt + 1) * 16);
            rb0 = *(const float4*)(Bb0 + (size_t)(kt + 1) * 16 * 64);
            rb1 = *(const float4*)(Bb1 + (size_t)(kt + 1) * 16 * 64);
        }
#pragma unroll
        for (int k = 0; k < 16; ++k) {
            float4 a0 = *(const float4*)&As[cur][k][ty * 8];
            float4 a1 = *(const float4*)&As[cur][k][ty * 8 + 4];
            const ull* bp = (const ull*)&Bs[cur][k][tx * 8];
            ull b0 = bp[0], b1 = bp[1], b2 = bp[2], b3 = bp[3];
            ull av;
            av = pack2_dup(a0.x); acc[0][0]=fma2(av,b0,acc[0][0]); acc[0][1]=fma2(av,b1,acc[0][1]); acc[0][2]=fma2(av,b2,acc[0][2]); acc[0][3]=fma2(av,b3,acc[0][3]);
            av = pack2_dup(a0.y); acc[1][0]=fma2(av,b0,acc[1][0]); acc[1][1]=fma2(av,b1,acc[1][1]); acc[1][2]=fma2(av,b2,acc[1][2]); acc[1][3]=fma2(av,b3,acc[1][3]);
            av = pack2_dup(a0.z); acc[2][0]=fma2(av,b0,acc[2][0]); acc[2][1]=fma2(av,b1,acc[2][1]); acc[2][2]=fma2(av,b2,acc[2][2]); acc[2][3]=fma2(av,b3,acc[2][3]);
            av = pack2_dup(a0.w); acc[3][0]=fma2(av,b0,acc[3][0]); acc[3][1]=fma2(av,b1,acc[3][1]); acc[3][2]=fma2(av,b2,acc[3][2]); acc[3][3]=fma2(av,b3,acc[3][3]);
            av = pack2_dup(a1.x); acc[4][0]=fma2(av,b0,acc[4][0]); acc[4][1]=fma2(av,b1,acc[4][1]); acc[4][2]=fma2(av,b2,acc[4][2]); acc[4][3]=fma2(av,b3,acc[4][3]);
            av = pack2_dup(a1.y); acc[5][0]=fma2(av,b0,acc[5][0]); acc[5][1]=fma2(av,b1,acc[5][1]); acc[5][2]=fma2(av,b2,acc[5][2]); acc[5][3]=fma2(av,b3,acc[5][3]);
            av = pack2_dup(a1.z); acc[6][0]=fma2(av,b0,acc[6][0]); acc[6][1]=fma2(av,b1,acc[6][1]); acc[6][2]=fma2(av,b2,acc[6][2]); acc[6][3]=fma2(av,b3,acc[6][3]);
            av = pack2_dup(a1.w); acc[7][0]=fma2(av,b0,acc[7][0]); acc[7][1]=fma2(av,b1,acc[7][1]); acc[7][2]=fma2(av,b2,acc[7][2]); acc[7][3]=fma2(av,b3,acc[7][3]);
        }
        if (kt + 1 < NT) {
            As[nxt][cA + 0][rA] = ra0.x; As[nxt][cA + 1][rA] = ra0.y;
            As[nxt][cA + 2][rA] = ra0.z; As[nxt][cA + 3][rA] = ra0.w;
            As[nxt][cA + 0][rA + 64] = ra1.x; As[nxt][cA + 1][rA + 64] = ra1.y;
            As[nxt][cA + 2][rA + 64] = ra1.z; As[nxt][cA + 3][rA + 64] = ra1.w;
            *(float4*)&Bs[nxt][kB    ][nB] = rb0;
            *(float4*)&Bs[nxt][kB + 8][nB] = rb1;
        }
        __syncthreads();
    }

    // epilogue: + b1, relu, * mixture, store to g_H
    const int ocol = col0 + tx * 8;
    const int leaf = ocol >> 6;        // 8 consecutive cols stay inside one leaf
    float bb[8];
    {
        float4 c0 = *(const float4*)(B1 + ocol);
        float4 c1 = *(const float4*)(B1 + ocol + 4);
        bb[0]=c0.x; bb[1]=c0.y; bb[2]=c0.z; bb[3]=c0.w;
        bb[4]=c1.x; bb[5]=c1.y; bb[6]=c1.z; bb[7]=c1.w;
    }
#pragma unroll
    for (int i = 0; i < 8; ++i) {
        const int row = row0 + ty * 8 + i;
        const float m = g_mix[row * NLEAF + leaf];
        float o[8];
#pragma unroll
        for (int j = 0; j < 4; ++j) unpack2(acc[i][j], o[2*j], o[2*j+1]);
#pragma unroll
        for (int j = 0; j < 8; ++j) {
            float v = o[j] + bb[j];
            v = v > 0.f ? v : 0.f;
            o[j] = v * m;
        }
        float4* dst = (float4*)(g_H + (size_t)row * HLD + ocol);
        dst[0] = make_float4(o[0], o[1], o[2], o[3]);
        dst[1] = make_float4(o[4], o[5], o[6], o[7]);
    }
}

// =====================================================================
// Kernel 3: out = H[:,0:4096] @ W2flat + mix @ b2s   (M=4096,N=512,K=4160)
// Bias rows folded as K rows 4096..4159 sourced from b2s.
// =====================================================================
__global__ __launch_bounds__(256) void gemm2_kernel(
    const float* __restrict__ W2,      // [4096, 512]  == w2s flat
    const float* __restrict__ B2,      // [64, 512]
    float* __restrict__ OUT)           // [4096, 512]
{
    __shared__ float As[2][16][128];
    __shared__ float Bs[2][16][128];

    const int tid = threadIdx.x;
    const int bn = blockIdx.x, bm = blockIdx.y;
    const int tx = tid & 15, ty = tid >> 4;
    const int row0 = bm * 128, col0 = bn * 128;

    const int rA = tid >> 2, cA = (tid & 3) * 4;
    const int kB = tid >> 5, nB = (tid & 31) * 4;
    const int nG = col0 + nB;

    const float* A0 = g_H + (size_t)(row0 + rA) * HLD + cA;
    const float* A1 = A0 + (size_t)64 * HLD;

    ull acc[8][4];
#pragma unroll
    for (int i = 0; i < 8; ++i)
#pragma unroll
        for (int j = 0; j < 4; ++j) acc[i][j] = 0ull;

    float4 ra0, ra1, rb0, rb1;

    // B row fetch with bias-fold branch
    auto bsrc = [&](int g) -> const float* {
        return (g < HCOLS) ? (W2 + (size_t)g * OUT_F + nG)
                           : (B2 + (size_t)(g - HCOLS) * OUT_F + nG);
    };

    ra0 = *(const float4*)(A0);
    ra1 = *(const float4*)(A1);
    rb0 = *(const float4*)bsrc(kB);
    rb1 = *(const float4*)bsrc(kB + 8);
    As[0][cA + 0][rA] = ra0.x; As[0][cA + 1][rA] = ra0.y;
    As[0][cA + 2][rA] = ra0.z; As[0][cA + 3][rA] = ra0.w;
    As[0][cA + 0][rA + 64] = ra1.x; As[0][cA + 1][rA + 64] = ra1.y;
    As[0][cA + 2][rA + 64] = ra1.z; As[0][cA + 3][rA + 64] = ra1.w;
    *(float4*)&Bs[0][kB    ][nB] = rb0;
    *(float4*)&Bs[0][kB + 8][nB] = rb1;
    __syncthreads();

    const int NT = HLD / 16;  // 260
    for (int kt = 0; kt < NT; ++kt) {
        const int cur = kt & 1, nxt = cur ^ 1;
        if (kt + 1 < NT) {
            ra0 = *(const float4*)(A0 + (kt + 1) * 16);
            ra1 = *(const float4*)(A1 + (kt + 1) * 16);
            rb0 = *(const float4*)bsrc((kt + 1) * 16 + kB);
            rb1 = *(const float4*)bsrc((kt + 1) * 16 + kB + 8);
        }
#pragma unroll
        for (int k = 0; k < 16; ++k) {
            float4 a0 = *(const float4*)&As[cur][k][ty * 8];
            float4 a1 = *(const float4*)&As[cur][k][ty * 8 + 4];
            const ull* bp = (const ull*)&Bs[cur][k][tx * 8];
            ull b0 = bp[0], b1 = bp[1], b2 = bp[2], b3 = bp[3];
            ull av;
            av = pack2_dup(a0.x); acc[0][0]=fma2(av,b0,acc[0][0]); acc[0][1]=fma2(av,b1,acc[0][1]); acc[0][2]=fma2(av,b2,acc[0][2]); acc[0][3]=fma2(av,b3,acc[0][3]);
            av = pack2_dup(a0.y); acc[1][0]=fma2(av,b0,acc[1][0]); acc[1][1]=fma2(av,b1,acc[1][1]); acc[1][2]=fma2(av,b2,acc[1][2]); acc[1][3]=fma2(av,b3,acc[1][3]);
            av = pack2_dup(a0.z); acc[2][0]=fma2(av,b0,acc[2][0]); acc[2][1]=fma2(av,b1,acc[2][1]); acc[2][2]=fma2(av,b2,acc[2][2]); acc[2][3]=fma2(av,b3,acc[2][3]);
            av = pack2_dup(a0.w); acc[3][0]=fma2(av,b0,acc[3][0]); acc[3][1]=fma2(av,b1,acc[3][1]); acc[3][2]=fma2(av,b2,acc[3][2]); acc[3][3]=fma2(av,b3,acc[3][3]);
            av = pack2_dup(a1.x); acc[4][0]=fma2(av,b0,acc[4][0]); acc[4][1]=fma2(av,b1,acc[4][1]); acc[4][2]=fma2(av,b2,acc[4][2]); acc[4][3]=fma2(av,b3,acc[4][3]);
            av = pack2_dup(a1.y); acc[5][0]=fma2(av,b0,acc[5][0]); acc[5][1]=fma2(av,b1,acc[5][1]); acc[5][2]=fma2(av,b2,acc[5][2]); acc[5][3]=fma2(av,b3,acc[5][3]);
            av = pack2_dup(a1.z); acc[6][0]=fma2(av,b0,acc[6][0]); acc[6][1]=fma2(av,b1,acc[6][1]); acc[6][2]=fma2(av,b2,acc[6][2]); acc[6][3]=fma2(av,b3,acc[6][3]);
            av = pack2_dup(a1.w); acc[7][0]=fma2(av,b0,acc[7][0]); acc[7][1]=fma2(av,b1,acc[7][1]); acc[7][2]=fma2(av,b2,acc[7][2]); acc[7][3]=fma2(av,b3,acc[7][3]);
        }
        if (kt + 1 < NT) {
            As[nxt][cA + 0][rA] = ra0.x; As[nxt][cA + 1][rA] = ra0.y;
            As[nxt][cA + 2][rA] = ra0.z; As[nxt][cA + 3][rA] = ra0.w;
            As[nxt][cA + 0][rA + 64] = ra1.x; As[nxt][cA + 1][rA + 64] = ra1.y;
            As[nxt][cA + 2][rA + 64] = ra1.z; As[nxt][cA + 3][rA + 64] = ra1.w;
            *(float4*)&Bs[nxt][kB    ][nB] = rb0;
            *(float4*)&Bs[nxt][kB + 8][nB] = rb1;
        }
        __syncthreads();
    }

    const int ocol = col0 + tx * 8;
#pragma unroll
    for (int i = 0; i < 8; ++i) {
        const int row = row0 + ty * 8 + i;
        float o[8];
#pragma unroll
        for (int j = 0; j < 4; ++j) unpack2(acc[i][j], o[2*j], o[2*j+1]);
        float4* dst = (float4*)(OUT + (size_t)row * OUT_F + ocol);
        dst[0] = make_float4(o[0], o[1], o[2], o[3]);
        dst[1] = make_float4(o[4], o[5], o[6], o[7]);
    }
}

// =====================================================================
extern "C" void kernel_launch(void* const* d_in, const int* in_sizes, int n_in,
                              void* d_out, int out_size) {
    const float* x   = (const float*)d_in[0];   // [4096,1024]
    const float* nw  = (const float*)d_in[1];   // [63,1024]
    const float* nb  = (const float*)d_in[2];   // [63,1]
    const float* w1s = (const float*)d_in[3];   // [64,1024,64]
    const float* b1s = (const float*)d_in[4];   // [64,64]
    const float* w2s = (const float*)d_in[5];   // [64,64,512]
    const float* b2s = (const float*)d_in[6];   // [64,512]
    float* out = (float*)d_out;                 // [4096,512]

    mix_kernel<<<B_ROWS, 256>>>(x, nw, nb);
    gemm1_kernel<<<dim3(HCOLS / 128, B_ROWS / 128), 256>>>(x, w1s, b1s);
    gemm2_kernel<<<dim3(OUT_F / 128, B_ROWS / 128), 256>>>(w2s, b2s, out);
}

// round 5
// speedup vs baseline: 2.0436x; 2.0436x over previous
#include <cuda_runtime.h>
#include <cuda_bf16.h>
#include <cstdint>
#include <math.h>

typedef unsigned long long ull;
typedef __nv_bfloat16 bf16;

#define B_ROWS 4096
#define IN_F   1024
#define NLEAF  64
#define OUT_F  512
#define HK     4160                 /* 4096 H cols + 64 mixture cols (b2s fold) */
#define STAGE_BYTES 32768           /* 16KB A + 16KB B per stage */
#define NSTAGE 3
#define SMEMSZ (NSTAGE*STAGE_BYTES)

// ---------------- device scratch ----------------
__device__ bf16 g_xh[B_ROWS*IN_F],  g_xl[B_ROWS*IN_F];
__device__ bf16 g_w1h[4096*1024],   g_w1l[4096*1024];   // [n=4096][k=1024]
__device__ bf16 g_w2h[512*HK],      g_w2l[512*HK];      // [o=512][k=4160]
__device__ bf16 g_Hh[(size_t)B_ROWS*HK], g_Hl[(size_t)B_ROWS*HK];
__device__ float g_mix[B_ROWS*NLEAF];

// ---------------- helpers ----------------
__device__ __forceinline__ void bsplit(float v, bf16 &h, bf16 &l){
    h = __float2bfloat16(v);
    l = __float2bfloat16(v - __bfloat162float(h));
}
__device__ __forceinline__ uint32_t s2u(const void* p){
    uint32_t a;
    asm("{ .reg .u64 t; cvta.to.shared.u64 t, %1; cvt.u32.u64 %0, t; }" : "=r"(a) : "l"(p));
    return a;
}
__device__ __forceinline__ void cpasync16(uint32_t dst, const void* src){
    asm volatile("cp.async.cg.shared.global [%0], [%1], 16;" :: "r"(dst), "l"(src) : "memory");
}
__device__ __forceinline__ void cp_commit(){ asm volatile("cp.async.commit_group;" ::: "memory"); }
__device__ __forceinline__ void ldsm4(uint32_t* r, uint32_t a){
    asm volatile("ldmatrix.sync.aligned.m8n8.x4.shared.b16 {%0,%1,%2,%3}, [%4];"
        : "=r"(r[0]), "=r"(r[1]), "=r"(r[2]), "=r"(r[3]) : "r"(a));
}
__device__ __forceinline__ void mma16816(float* c, const uint32_t* a, uint32_t b0, uint32_t b1){
    asm volatile("mma.sync.aligned.m16n8k16.row.col.f32.bf16.bf16.f32 "
        "{%0,%1,%2,%3}, {%4,%5,%6,%7}, {%8,%9}, {%0,%1,%2,%3};"
        : "+f"(c[0]), "+f"(c[1]), "+f"(c[2]), "+f"(c[3])
        : "r"(a[0]), "r"(a[1]), "r"(a[2]), "r"(a[3]), "r"(b0), "r"(b1));
}

// =====================================================================
// Conversion kernels: fp32 -> (hi,lo) bf16 split (+transposes for B operands)
// =====================================================================
__global__ __launch_bounds__(256) void convx_kernel(const float* __restrict__ x){
    int i = blockIdx.x*256 + threadIdx.x;
    float4 v = ((const float4*)x)[i];
    __align__(8) bf16 h[4], l[4];
    bsplit(v.x,h[0],l[0]); bsplit(v.y,h[1],l[1]); bsplit(v.z,h[2],l[2]); bsplit(v.w,h[3],l[3]);
    *(ull*)&g_xh[(size_t)i*4] = *(ull*)h;
    *(ull*)&g_xl[(size_t)i*4] = *(ull*)l;
}

__global__ __launch_bounds__(256) void convw1_kernel(const float* __restrict__ w1){
    __shared__ float s[64][65];
    const int kc = blockIdx.x, l = blockIdx.y, tid = threadIdx.x;
    const float* src = w1 + ((size_t)l*1024 + kc*64)*64;
    for (int u = tid; u < 4096; u += 256) s[u>>6][u&63] = src[u];
    __syncthreads();
    const int w = tid>>2, i0 = (tid&3)*16;
    __align__(16) bf16 hh[16], ll[16];
#pragma unroll
    for (int i=0;i<16;i++) bsplit(s[i0+i][w], hh[i], ll[i]);
    size_t off = (size_t)(l*64+w)*1024 + kc*64 + i0;
    *(uint4*)&g_w1h[off]   = ((uint4*)hh)[0]; *(uint4*)&g_w1h[off+8] = ((uint4*)hh)[1];
    *(uint4*)&g_w1l[off]   = ((uint4*)ll)[0]; *(uint4*)&g_w1l[off+8] = ((uint4*)ll)[1];
}

__global__ __launch_bounds__(256) void convw2_kernel(const float* __restrict__ w2){
    __shared__ float s[64][65];
    const int ot = blockIdx.x, rt = blockIdx.y, tid = threadIdx.x;
    for (int u = tid; u < 4096; u += 256)
        s[u>>6][u&63] = w2[(size_t)(rt*64 + (u>>6))*512 + ot*64 + (u&63)];
    __syncthreads();
    const int o = tid>>2, i0 = (tid&3)*16;
    __align__(16) bf16 hh[16], ll[16];
#pragma unroll
    for (int i=0;i<16;i++) bsplit(s[i0+i][o], hh[i], ll[i]);
    size_t off = (size_t)(ot*64+o)*HK + rt*64 + i0;
    *(uint4*)&g_w2h[off]   = ((uint4*)hh)[0]; *(uint4*)&g_w2h[off+8] = ((uint4*)hh)[1];
    *(uint4*)&g_w2l[off]   = ((uint4*)ll)[0]; *(uint4*)&g_w2l[off+8] = ((uint4*)ll)[1];
}

__global__ __launch_bounds__(256) void convtail_kernel(const float* __restrict__ b2){
    __shared__ float s[64][65];
    const int ot = blockIdx.x, tid = threadIdx.x;
    for (int u = tid; u < 4096; u += 256)
        s[u>>6][u&63] = b2[(size_t)(u>>6)*512 + ot*64 + (u&63)];
    __syncthreads();
    const int o = tid>>2, j0 = (tid&3)*16;
    __align__(16) bf16 hh[16], ll[16];
#pragma unroll
    for (int i=0;i<16;i++) bsplit(s[j0+i][o], hh[i], ll[i]);
    size_t off = (size_t)(ot*64+o)*HK + 4096 + j0;
    *(uint4*)&g_w2h[off]   = ((uint4*)hh)[0]; *(uint4*)&g_w2h[off+8] = ((uint4*)hh)[1];
    *(uint4*)&g_w2l[off]   = ((uint4*)ll)[0]; *(uint4*)&g_w2l[off+8] = ((uint4*)ll)[1];
}

// =====================================================================
// Routing tree: 8 batch rows/block. Writes g_mix + hi/lo mixture tail of H.
// =====================================================================
__global__ __launch_bounds__(256) void mix_kernel(
    const float* __restrict__ x, const float* __restrict__ nw, const float* __restrict__ nb)
{
    __shared__ float xs[8*1024];
    __shared__ float lg[8][64];
    const int tid = threadIdx.x, warp = tid>>5, lane = tid&31;
    const int b0 = blockIdx.x * 8;

    for (int u = tid; u < 2048; u += 256)
        ((float4*)xs)[u] = ((const float4*)(x + (size_t)b0*IN_F))[u];
    __syncthreads();

    {
        float acc[8][8];
#pragma unroll
        for (int t=0;t<8;t++)
#pragma unroll
            for (int r=0;r<8;r++) acc[t][r] = 0.f;
        const float* wp[8];
#pragma unroll
        for (int t=0;t<8;t++){
            int nn = warp + 8*t;
            wp[t] = nw + (size_t)((nn < 63) ? nn : 0)*IN_F;
        }
        for (int j = 0; j < 32; ++j){
            const int o = lane + 32*j;
            float xv[8];
#pragma unroll
            for (int r=0;r<8;r++) xv[r] = xs[r*1024 + o];
#pragma unroll
            for (int t=0;t<8;t++){
                float wv = wp[t][o];
#pragma unroll
                for (int r=0;r<8;r++) acc[t][r] += xv[r]*wv;
            }
        }
#pragma unroll
        for (int t=0;t<8;t++){
            int nn = warp + 8*t;
#pragma unroll
            for (int r=0;r<8;r++){
                float s = acc[t][r];
#pragma unroll
                for (int o=16;o>0;o>>=1) s += __shfl_xor_sync(0xffffffffu, s, o);
                if (lane==0 && nn<63) lg[r][nn] = s + nb[nn];
            }
        }
    }
    __syncthreads();

#pragma unroll
    for (int p=0;p<2;p++){
        const int idx = tid + 256*p;
        const int r = idx>>6, l = idx&63;
        float m = 1.f;
#pragma unroll
        for (int d=0; d<6; ++d){
            int nidx = (1<<d) - 1 + (l >> (6-d));
            float sg = 1.f/(1.f + expf(-lg[r][nidx]));
            m *= ((l >> (5-d)) & 1) ? sg : (1.f - sg);
        }
        g_mix[(size_t)(b0+r)*NLEAF + l] = m;
        bf16 h, lo; bsplit(m, h, lo);
        g_Hh[(size_t)(b0+r)*HK + 4096 + l] = h;
        g_Hl[(size_t)(b0+r)*HK + 4096 + l] = lo;
    }
}

// =====================================================================
// HMMA split-bf16 GEMM: 128x128 tile, BK=64, 3-stage cp.async pipeline.
// 3 accumulation passes (Ah*Bh, Al*Bh, Ah*Bl) into fp32 accumulators.
// Operands stored [n][k] k-contiguous (row.col mma: A row-major, B col-major).
// EPI 1: bias+relu+mix -> Hh/Hl bf16.   EPI 2: plain fp32 store.
// =====================================================================
template<int KTOT, int EPI>
__global__ __launch_bounds__(256,2) void gemm_mma(const float* __restrict__ bias,
                                                  float* __restrict__ outp)
{
    extern __shared__ __align__(1024) char dsm[];
    const uint32_t smem0 = s2u(dsm);

    const int tid = threadIdx.x, wid = tid>>5, lane = tid&31;
    const int row0 = blockIdx.y*128, col0 = blockIdx.x*128;

    // warp tile: 2 (m) x 4 (n) warps; warp covers 64 m-rows, 32 n-cols
    const int wm = wid>>2, wn = wid&3;
    const int m0 = wm*64, n0 = wn*32;

    const bf16 *Ah, *Al, *Bh, *Bl;
    if (EPI==1){ Ah=g_xh; Al=g_xl; Bh=g_w1h; Bl=g_w1l; }
    else       { Ah=g_Hh; Al=g_Hl; Bh=g_w2h; Bl=g_w2l; }
    const int NCH = KTOT/64, TOT = NCH*3;

    // ---- cp.async mapping: thread handles 64B (4x16B) of one 128B row ----
    const int lr = tid>>1;                 // tile row 0..127
    const int lhe = (tid&1)*32;            // element offset (32 bf16 = 64B)
    const uint32_t dstrelA = lr*128 + (((lr&7)<<4) ^ ((tid&1)*64));
    const bf16* Arow_h = Ah + (size_t)(row0+lr)*KTOT + lhe;
    const bf16* Arow_l = Al + (size_t)(row0+lr)*KTOT + lhe;
    const bf16* Brow_h = Bh + (size_t)(col0+lr)*KTOT + lhe;
    const bf16* Brow_l = Bl + (size_t)(col0+lr)*KTOT + lhe;

    // ---- ldmatrix per-lane relative offsets (swizzle folded in) ----
    uint32_t relA[4], relB[2];
    {
        const int mat = lane>>3, r = lane&7;
        const int cfA = (mat>>1)*16;
#pragma unroll
        for (int mi=0; mi<4; ++mi){
            int row = m0 + mi*16 + (mat&1)*8 + r;
            relA[mi] = row*128 + ((((row&7)<<4) ^ cfA));
        }
        const int cfB = (mat&1)*16;
#pragma unroll
        for (int j=0; j<2; ++j){
            int row = n0 + j*16 + (mat>>1)*8 + r;
            relB[j] = row*128 + ((((row&7)<<4) ^ cfB));
        }
    }

    float acc[4][4][4];
#pragma unroll
    for (int mi=0;mi<4;mi++)
#pragma unroll
        for (int ni=0;ni<4;ni++)
#pragma unroll
            for (int q=0;q<4;q++) acc[mi][ni][q] = 0.f;

    // ---- issue one chunk into stage s ----
    auto issue = [&](int c, int s){
        const int pass = c / NCH;
        const int kk = (c - pass*NCH) * 64;
        const bf16* As = (pass==1 ? Arow_l : Arow_h) + kk;
        const bf16* Bs = (pass==2 ? Brow_l : Brow_h) + kk;
        const uint32_t da = smem0 + s*STAGE_BYTES + dstrelA;
        const uint32_t db = da + 16384;
#pragma unroll
        for (int i=0;i<4;i++) cpasync16(da ^ (i*16), As + i*8);
#pragma unroll
        for (int i=0;i<4;i++) cpasync16(db ^ (i*16), Bs + i*8);
        cp_commit();
    };

    issue(0, 0);
    issue(1, 1);

    for (int c = 0; c < TOT; ++c){
        if (c == TOT-1) asm volatile("cp.async.wait_group 0;" ::: "memory");
        else            asm volatile("cp.async.wait_group 1;" ::: "memory");
        __syncthreads();
        if (c+2 < TOT) issue(c+2, (c+2)%3);

        const uint32_t sA = smem0 + (c%3)*STAGE_BYTES;
        const uint32_t sB = sA + 16384;
#pragma unroll
        for (int ks=0; ks<4; ++ks){
            const uint32_t kx = ks*32;
            uint32_t a[4][4], bm[2][4];
#pragma unroll
            for (int mi=0;mi<4;mi++) ldsm4(a[mi], sA + (relA[mi] ^ kx));
#pragma unroll
            for (int j=0;j<2;j++)    ldsm4(bm[j], sB + (relB[j] ^ kx));
#pragma unroll
            for (int mi=0;mi<4;mi++)
#pragma unroll
                for (int ni=0;ni<4;ni++)
                    mma16816(acc[mi][ni], a[mi], bm[ni>>1][(ni&1)*2], bm[ni>>1][(ni&1)*2+1]);
        }
    }

    // ---- epilogue ----
    const int g = lane>>2, tig = lane&3;
    const int leaf = (col0 + n0) >> 6;      // 32-col warp tile never crosses a leaf
#pragma unroll
    for (int mi=0; mi<4; ++mi){
        const int ra = row0 + m0 + mi*16 + g;
        float mx0 = 0.f, mx1 = 0.f;
        if (EPI == 1){
            mx0 = g_mix[(size_t)ra*NLEAF + leaf];
            mx1 = g_mix[(size_t)(ra+8)*NLEAF + leaf];
        }
#pragma unroll
        for (int ni=0; ni<4; ++ni){
            const int col = col0 + n0 + ni*8 + tig*2;
            if (EPI == 1){
                const float b0v = bias[col], b1v = bias[col+1];
                float v00 = fmaxf(acc[mi][ni][0] + b0v, 0.f) * mx0;
                float v01 = fmaxf(acc[mi][ni][1] + b1v, 0.f) * mx0;
                float v10 = fmaxf(acc[mi][ni][2] + b0v, 0.f) * mx1;
                float v11 = fmaxf(acc[mi][ni][3] + b1v, 0.f) * mx1;
                __align__(4) bf16 h0[2], l0[2], h1[2], l1[2];
                bsplit(v00, h0[0], l0[0]); bsplit(v01, h0[1], l0[1]);
                bsplit(v10, h1[0], l1[0]); bsplit(v11, h1[1], l1[1]);
                *(uint32_t*)&g_Hh[(size_t)ra*HK + col]     = *(uint32_t*)h0;
                *(uint32_t*)&g_Hl[(size_t)ra*HK + col]     = *(uint32_t*)l0;
                *(uint32_t*)&g_Hh[(size_t)(ra+8)*HK + col] = *(uint32_t*)h1;
                *(uint32_t*)&g_Hl[(size_t)(ra+8)*HK + col] = *(uint32_t*)l1;
            } else {
                *(float2*)&outp[(size_t)ra*OUT_F + col]     = make_float2(acc[mi][ni][0], acc[mi][ni][1]);
                *(float2*)&outp[(size_t)(ra+8)*OUT_F + col] = make_float2(acc[mi][ni][2], acc[mi][ni][3]);
            }
        }
    }
}

// =====================================================================
extern "C" void kernel_launch(void* const* d_in, const int* in_sizes, int n_in,
                              void* d_out, int out_size) {
    const float* x   = (const float*)d_in[0];   // [4096,1024]
    const float* nw  = (const float*)d_in[1];   // [63,1024]
    const float* nb  = (const float*)d_in[2];   // [63,1]
    const float* w1s = (const float*)d_in[3];   // [64,1024,64]
    const float* b1s = (const float*)d_in[4];   // [64,64] flat = H column
    const float* w2s = (const float*)d_in[5];   // [64,64,512] flat = [4096,512]
    const float* b2s = (const float*)d_in[6];   // [64,512]
    float* out = (float*)d_out;                 // [4096,512]

    cudaFuncSetAttribute(gemm_mma<IN_F,1>, cudaFuncAttributeMaxDynamicSharedMemorySize, SMEMSZ);
    cudaFuncSetAttribute(gemm_mma<HK,2>,   cudaFuncAttributeMaxDynamicSharedMemorySize, SMEMSZ);

    convx_kernel   <<<4096, 256>>>(x);
    convw1_kernel  <<<dim3(16,64), 256>>>(w1s);
    convw2_kernel  <<<dim3(8,64),  256>>>(w2s);
    convtail_kernel<<<8, 256>>>(b2s);
    mix_kernel     <<<512, 256>>>(x, nw, nb);

    gemm_mma<IN_F,1><<<dim3(32,32), 256, SMEMSZ>>>(b1s, nullptr);   // H = relu(x@W1+b1)*mix
    gemm_mma<HK,2>  <<<dim3(4,32),  256, SMEMSZ>>>(nullptr, out);   // out = Hm@W2 + mix@b2
}

// round 6
// speedup vs baseline: 2.1752x; 1.0644x over previous
#include <cuda_runtime.h>
#include <cuda_bf16.h>
#include <cstdint>
#include <math.h>

typedef unsigned long long ull;
typedef __nv_bfloat16 bf16;

#define B_ROWS 4096
#define IN_F   1024
#define NLEAF  64
#define OUT_F  512
#define HK     4160                 /* 4096 H cols + 64 mixture cols (b2s fold) */
#define STAGE_BYTES 65536           /* Ah,Al,Bh,Bl tiles: 4 x 16KB per stage */
#define SMEMSZ (3*STAGE_BYTES)      /* 192KB, 1 CTA/SM */

// ---------------- device scratch ----------------
__device__ bf16 g_xh[B_ROWS*IN_F],  g_xl[B_ROWS*IN_F];
__device__ bf16 g_w1h[4096*1024],   g_w1l[4096*1024];   // [n=4096][k=1024]
__device__ bf16 g_w2h[512*HK],      g_w2l[512*HK];      // [o=512][k=4160]
__device__ bf16 g_Hh[(size_t)B_ROWS*HK], g_Hl[(size_t)B_ROWS*HK];
__device__ float g_mix[B_ROWS*NLEAF];

// ---------------- helpers ----------------
__device__ __forceinline__ void bsplit(float v, bf16 &h, bf16 &l){
    h = __float2bfloat16(v);
    l = __float2bfloat16(v - __bfloat162float(h));
}
__device__ __forceinline__ uint32_t s2u(const void* p){
    uint32_t a;
    asm("{ .reg .u64 t; cvta.to.shared.u64 t, %1; cvt.u32.u64 %0, t; }" : "=r"(a) : "l"(p));
    return a;
}
__device__ __forceinline__ void cpasync16(uint32_t dst, const void* src){
    asm volatile("cp.async.cg.shared.global [%0], [%1], 16;" :: "r"(dst), "l"(src) : "memory");
}
__device__ __forceinline__ void cp_commit(){ asm volatile("cp.async.commit_group;" ::: "memory"); }
__device__ __forceinline__ void ldsm4(uint32_t* r, uint32_t a){
    asm volatile("ldmatrix.sync.aligned.m8n8.x4.shared.b16 {%0,%1,%2,%3}, [%4];"
        : "=r"(r[0]), "=r"(r[1]), "=r"(r[2]), "=r"(r[3]) : "r"(a));
}
__device__ __forceinline__ void mma16816(float* c, const uint32_t* a, uint32_t b0, uint32_t b1){
    asm volatile("mma.sync.aligned.m16n8k16.row.col.f32.bf16.bf16.f32 "
        "{%0,%1,%2,%3}, {%4,%5,%6,%7}, {%8,%9}, {%0,%1,%2,%3};"
        : "+f"(c[0]), "+f"(c[1]), "+f"(c[2]), "+f"(c[3])
        : "r"(a[0]), "r"(a[1]), "r"(a[2]), "r"(a[3]), "r"(b0), "r"(b1));
}

// =====================================================================
// Conversion kernels: fp32 -> (hi,lo) bf16 split (+transposes for B operands)
// =====================================================================
__global__ __launch_bounds__(256) void convx_kernel(const float* __restrict__ x){
    int i = blockIdx.x*256 + threadIdx.x;
    float4 v = ((const float4*)x)[i];
    __align__(8) bf16 h[4], l[4];
    bsplit(v.x,h[0],l[0]); bsplit(v.y,h[1],l[1]); bsplit(v.z,h[2],l[2]); bsplit(v.w,h[3],l[3]);
    *(ull*)&g_xh[(size_t)i*4] = *(ull*)h;
    *(ull*)&g_xl[(size_t)i*4] = *(ull*)l;
}

__global__ __launch_bounds__(256) void convw1_kernel(const float* __restrict__ w1){
    __shared__ float s[64][65];
    const int kc = blockIdx.x, l = blockIdx.y, tid = threadIdx.x;
    const float* src = w1 + ((size_t)l*1024 + kc*64)*64;
    for (int u = tid; u < 4096; u += 256) s[u>>6][u&63] = src[u];
    __syncthreads();
    const int w = tid>>2, i0 = (tid&3)*16;
    __align__(16) bf16 hh[16], ll[16];
#pragma unroll
    for (int i=0;i<16;i++) bsplit(s[i0+i][w], hh[i], ll[i]);
    size_t off = (size_t)(l*64+w)*1024 + kc*64 + i0;
    *(uint4*)&g_w1h[off]   = ((uint4*)hh)[0]; *(uint4*)&g_w1h[off+8] = ((uint4*)hh)[1];
    *(uint4*)&g_w1l[off]   = ((uint4*)ll)[0]; *(uint4*)&g_w1l[off+8] = ((uint4*)ll)[1];
}

__global__ __launch_bounds__(256) void convw2_kernel(const float* __restrict__ w2){
    __shared__ float s[64][65];
    const int ot = blockIdx.x, rt = blockIdx.y, tid = threadIdx.x;
    for (int u = tid; u < 4096; u += 256)
        s[u>>6][u&63] = w2[(size_t)(rt*64 + (u>>6))*512 + ot*64 + (u&63)];
    __syncthreads();
    const int o = tid>>2, i0 = (tid&3)*16;
    __align__(16) bf16 hh[16], ll[16];
#pragma unroll
    for (int i=0;i<16;i++) bsplit(s[i0+i][o], hh[i], ll[i]);
    size_t off = (size_t)(ot*64+o)*HK + rt*64 + i0;
    *(uint4*)&g_w2h[off]   = ((uint4*)hh)[0]; *(uint4*)&g_w2h[off+8] = ((uint4*)hh)[1];
    *(uint4*)&g_w2l[off]   = ((uint4*)ll)[0]; *(uint4*)&g_w2l[off+8] = ((uint4*)ll)[1];
}

__global__ __launch_bounds__(256) void convtail_kernel(const float* __restrict__ b2){
    __shared__ float s[64][65];
    const int ot = blockIdx.x, tid = threadIdx.x;
    for (int u = tid; u < 4096; u += 256)
        s[u>>6][u&63] = b2[(size_t)(u>>6)*512 + ot*64 + (u&63)];
    __syncthreads();
    const int o = tid>>2, j0 = (tid&3)*16;
    __align__(16) bf16 hh[16], ll[16];
#pragma unroll
    for (int i=0;i<16;i++) bsplit(s[j0+i][o], hh[i], ll[i]);
    size_t off = (size_t)(ot*64+o)*HK + 4096 + j0;
    *(uint4*)&g_w2h[off]   = ((uint4*)hh)[0]; *(uint4*)&g_w2h[off+8] = ((uint4*)hh)[1];
    *(uint4*)&g_w2l[off]   = ((uint4*)ll)[0]; *(uint4*)&g_w2l[off+8] = ((uint4*)ll)[1];
}

// =====================================================================
// Routing tree: 8 batch rows/block. Writes g_mix + hi/lo mixture tail of H.
// =====================================================================
__global__ __launch_bounds__(256) void mix_kernel(
    const float* __restrict__ x, const float* __restrict__ nw, const float* __restrict__ nb)
{
    __shared__ float xs[8*1024];
    __shared__ float lg[8][64];
    const int tid = threadIdx.x, warp = tid>>5, lane = tid&31;
    const int b0 = blockIdx.x * 8;

    for (int u = tid; u < 2048; u += 256)
        ((float4*)xs)[u] = ((const float4*)(x + (size_t)b0*IN_F))[u];
    __syncthreads();

    {
        float acc[8][8];
#pragma unroll
        for (int t=0;t<8;t++)
#pragma unroll
            for (int r=0;r<8;r++) acc[t][r] = 0.f;
        const float* wp[8];
#pragma unroll
        for (int t=0;t<8;t++){
            int nn = warp + 8*t;
            wp[t] = nw + (size_t)((nn < 63) ? nn : 0)*IN_F;
        }
        for (int j = 0; j < 32; ++j){
            const int o = lane + 32*j;
            float xv[8];
#pragma unroll
            for (int r=0;r<8;r++) xv[r] = xs[r*1024 + o];
#pragma unroll
            for (int t=0;t<8;t++){
                float wv = wp[t][o];
#pragma unroll
                for (int r=0;r<8;r++) acc[t][r] += xv[r]*wv;
            }
        }
#pragma unroll
        for (int t=0;t<8;t++){
            int nn = warp + 8*t;
#pragma unroll
            for (int r=0;r<8;r++){
                float s = acc[t][r];
#pragma unroll
                for (int o=16;o>0;o>>=1) s += __shfl_xor_sync(0xffffffffu, s, o);
                if (lane==0 && nn<63) lg[r][nn] = s + nb[nn];
            }
        }
    }
    __syncthreads();

#pragma unroll
    for (int p=0;p<2;p++){
        const int idx = tid + 256*p;
        const int r = idx>>6, l = idx&63;
        float m = 1.f;
#pragma unroll
        for (int d=0; d<6; ++d){
            int nidx = (1<<d) - 1 + (l >> (6-d));
            float sg = 1.f/(1.f + expf(-lg[r][nidx]));
            m *= ((l >> (5-d)) & 1) ? sg : (1.f - sg);
        }
        g_mix[(size_t)(b0+r)*NLEAF + l] = m;
        bf16 h, lo; bsplit(m, h, lo);
        g_Hh[(size_t)(b0+r)*HK + 4096 + l] = h;
        g_Hl[(size_t)(b0+r)*HK + 4096 + l] = lo;
    }
}

// =====================================================================
// HMMA split-bf16 GEMM, fused passes: per 64-wide k-chunk load Ah,Al,Bh,Bl
// once and accumulate Ah*Bh + Al*Bh + Ah*Bl. 128x128 tile, 3-stage pipeline
// (64KB/stage), 1 CTA/SM, 8 warps (2m x 4n), warp tile 64x32.
// EPI 1: bias+relu+mix -> Hh/Hl bf16.   EPI 2: plain fp32 store.
// =====================================================================
template<int KTOT, int EPI>
__global__ __launch_bounds__(256,1) void gemm_mma(const float* __restrict__ bias,
                                                  float* __restrict__ outp)
{
    extern __shared__ __align__(1024) char dsm[];
    const uint32_t smem0 = s2u(dsm);

    const int tid = threadIdx.x, wid = tid>>5, lane = tid&31;
    const int row0 = blockIdx.y*128, col0 = blockIdx.x*128;

    const int wm = wid>>2, wn = wid&3;
    const int m0 = wm*64, n0 = wn*32;

    const bf16 *Ah, *Al, *Bh, *Bl;
    if (EPI==1){ Ah=g_xh; Al=g_xl; Bh=g_w1h; Bl=g_w1l; }
    else       { Ah=g_Hh; Al=g_Hl; Bh=g_w2h; Bl=g_w2l; }
    const int TOT = KTOT/64;

    // ---- cp.async mapping: thread handles 64B (4x16B) of one 128B tile row ----
    const int lr = tid>>1;
    const int lhe = (tid&1)*32;
    const uint32_t dstrel = lr*128 + (((lr&7)<<4) ^ ((tid&1)*64));
    const bf16* Arow_h = Ah + (size_t)(row0+lr)*KTOT + lhe;
    const bf16* Arow_l = Al + (size_t)(row0+lr)*KTOT + lhe;
    const bf16* Brow_h = Bh + (size_t)(col0+lr)*KTOT + lhe;
    const bf16* Brow_l = Bl + (size_t)(col0+lr)*KTOT + lhe;

    // ---- ldmatrix per-lane relative offsets (SW128 folded in) ----
    uint32_t relA[4], relB[2];
    {
        const int mat = lane>>3, r = lane&7;
        const int cfA = (mat>>1)*16;
#pragma unroll
        for (int mi=0; mi<4; ++mi){
            int row = m0 + mi*16 + (mat&1)*8 + r;
            relA[mi] = row*128 + ((((row&7)<<4) ^ cfA));
        }
        const int cfB = (mat&1)*16;
#pragma unroll
        for (int j=0; j<2; ++j){
            int row = n0 + j*16 + (mat>>1)*8 + r;
            relB[j] = row*128 + ((((row&7)<<4) ^ cfB));
        }
    }

    float acc[4][4][4];
#pragma unroll
    for (int mi=0;mi<4;mi++)
#pragma unroll
        for (int ni=0;ni<4;ni++)
#pragma unroll
            for (int q=0;q<4;q++) acc[mi][ni][q] = 0.f;

    // ---- issue chunk c into stage s: 4 tiles (Ah | Al | Bh | Bl) ----
    auto issue = [&](int c, int s){
        const int kk = c*64;
        const uint32_t d0 = smem0 + s*STAGE_BYTES + dstrel;
        const bf16* pah = Arow_h + kk;
        const bf16* pal = Arow_l + kk;
        const bf16* pbh = Brow_h + kk;
        const bf16* pbl = Brow_l + kk;
#pragma unroll
        for (int i=0;i<4;i++) cpasync16( d0           ^ (i*16), pah + i*8);
#pragma unroll
        for (int i=0;i<4;i++) cpasync16((d0 + 16384) ^ (i*16), pal + i*8);
#pragma unroll
        for (int i=0;i<4;i++) cpasync16((d0 + 32768) ^ (i*16), pbh + i*8);
#pragma unroll
        for (int i=0;i<4;i++) cpasync16((d0 + 49152) ^ (i*16), pbl + i*8);
        cp_commit();
    };

    issue(0, 0);
    issue(1, 1);

    for (int c = 0; c < TOT; ++c){
        if (c == TOT-1) asm volatile("cp.async.wait_group 0;" ::: "memory");
        else            asm volatile("cp.async.wait_group 1;" ::: "memory");
        __syncthreads();
        if (c+2 < TOT) issue(c+2, (c+2)%3);

        const uint32_t sAh = smem0 + (c%3)*STAGE_BYTES;
        const uint32_t sAl = sAh + 16384;
        const uint32_t sBh = sAh + 32768;
        const uint32_t sBl = sAh + 49152;
#pragma unroll
        for (int ks=0; ks<4; ++ks){
            const uint32_t kx = ks*32;
            uint32_t ah[4][4], al[4][4], bh[2][4], bl[2][4];
#pragma unroll
            for (int mi=0;mi<4;mi++) ldsm4(ah[mi], sAh + (relA[mi] ^ kx));
#pragma unroll
            for (int j=0;j<2;j++)    ldsm4(bh[j], sBh + (relB[j] ^ kx));
#pragma unroll
            for (int mi=0;mi<4;mi++) ldsm4(al[mi], sAl + (relA[mi] ^ kx));
#pragma unroll
            for (int j=0;j<2;j++)    ldsm4(bl[j], sBl + (relB[j] ^ kx));
            // pass0: Ah*Bh
#pragma unroll
            for (int mi=0;mi<4;mi++)
#pragma unroll
                for (int ni=0;ni<4;ni++)
                    mma16816(acc[mi][ni], ah[mi], bh[ni>>1][(ni&1)*2], bh[ni>>1][(ni&1)*2+1]);
            // pass1: Al*Bh
#pragma unroll
            for (int mi=0;mi<4;mi++)
#pragma unroll
                for (int ni=0;ni<4;ni++)
                    mma16816(acc[mi][ni], al[mi], bh[ni>>1][(ni&1)*2], bh[ni>>1][(ni&1)*2+1]);
            // pass2: Ah*Bl
#pragma unroll
            for (int mi=0;mi<4;mi++)
#pragma unroll
                for (int ni=0;ni<4;ni++)
                    mma16816(acc[mi][ni], ah[mi], bl[ni>>1][(ni&1)*2], bl[ni>>1][(ni&1)*2+1]);
        }
    }

    // ---- epilogue ----
    const int g = lane>>2, tig = lane&3;
    const int leaf = (col0 + n0) >> 6;      // 32-col warp tile never crosses a leaf
#pragma unroll
    for (int mi=0; mi<4; ++mi){
        const int ra = row0 + m0 + mi*16 + g;
        float mx0 = 0.f, mx1 = 0.f;
        if (EPI == 1){
            mx0 = g_mix[(size_t)ra*NLEAF + leaf];
            mx1 = g_mix[(size_t)(ra+8)*NLEAF + leaf];
        }
#pragma unroll
        for (int ni=0; ni<4; ++ni){
            const int col = col0 + n0 + ni*8 + tig*2;
            if (EPI == 1){
                const float b0v = bias[col], b1v = bias[col+1];
                float v00 = fmaxf(acc[mi][ni][0] + b0v, 0.f) * mx0;
                float v01 = fmaxf(acc[mi][ni][1] + b1v, 0.f) * mx0;
                float v10 = fmaxf(acc[mi][ni][2] + b0v, 0.f) * mx1;
                float v11 = fmaxf(acc[mi][ni][3] + b1v, 0.f) * mx1;
                __align__(4) bf16 h0[2], l0[2], h1[2], l1[2];
                bsplit(v00, h0[0], l0[0]); bsplit(v01, h0[1], l0[1]);
                bsplit(v10, h1[0], l1[0]); bsplit(v11, h1[1], l1[1]);
                *(uint32_t*)&g_Hh[(size_t)ra*HK + col]     = *(uint32_t*)h0;
                *(uint32_t*)&g_Hl[(size_t)ra*HK + col]     = *(uint32_t*)l0;
                *(uint32_t*)&g_Hh[(size_t)(ra+8)*HK + col] = *(uint32_t*)h1;
                *(uint32_t*)&g_Hl[(size_t)(ra+8)*HK + col] = *(uint32_t*)l1;
            } else {
                *(float2*)&outp[(size_t)ra*OUT_F + col]     = make_float2(acc[mi][ni][0], acc[mi][ni][1]);
                *(float2*)&outp[(size_t)(ra+8)*OUT_F + col] = make_float2(acc[mi][ni][2], acc[mi][ni][3]);
            }
        }
    }
}

// =====================================================================
extern "C" void kernel_launch(void* const* d_in, const int* in_sizes, int n_in,
                              void* d_out, int out_size) {
    const float* x   = (const float*)d_in[0];   // [4096,1024]
    const float* nw  = (const float*)d_in[1];   // [63,1024]
    const float* nb  = (const float*)d_in[2];   // [63,1]
    const float* w1s = (const float*)d_in[3];   // [64,1024,64]
    const float* b1s = (const float*)d_in[4];   // [64,64] flat = H column
    const float* w2s = (const float*)d_in[5];   // [64,64,512] flat = [4096,512]
    const float* b2s = (const float*)d_in[6];   // [64,512]
    float* out = (float*)d_out;                 // [4096,512]

    cudaFuncSetAttribute(gemm_mma<IN_F,1>, cudaFuncAttributeMaxDynamicSharedMemorySize, SMEMSZ);
    cudaFuncSetAttribute(gemm_mma<HK,2>,   cudaFuncAttributeMaxDynamicSharedMemorySize, SMEMSZ);

    convx_kernel   <<<4096, 256>>>(x);
    convw1_kernel  <<<dim3(16,64), 256>>>(w1s);
    convw2_kernel  <<<dim3(8,64),  256>>>(w2s);
    convtail_kernel<<<8, 256>>>(b2s);
    mix_kernel     <<<512, 256>>>(x, nw, nb);

    gemm_mma<IN_F,1><<<dim3(32,32), 256, SMEMSZ>>>(b1s, nullptr);   // H = relu(x@W1+b1)*mix
    gemm_mma<HK,2>  <<<dim3(4,32),  256, SMEMSZ>>>(nullptr, out);   // out = Hm@W2 + mix@b2
}

// round 7
// speedup vs baseline: 2.5608x; 1.1773x over previous
#include <cuda_runtime.h>
#include <cuda_bf16.h>
#include <cstdint>
#include <math.h>

typedef unsigned long long ull;
typedef __nv_bfloat16 bf16;

#define B_ROWS 4096
#define IN_F   1024
#define NLEAF  64
#define OUT_F  512
#define HK     4160                 /* 4096 H cols + 64 mixture cols (b2s fold) */
#define STAGE_BYTES 65536           /* Ah,Al,Bh,Bl tiles: 4 x 16KB per stage */
#define SMEMSZ (3*STAGE_BYTES)      /* 192KB, 1 CTA/SM */

// ---------------- device scratch ----------------
__device__ bf16 g_xh[B_ROWS*IN_F],  g_xl[B_ROWS*IN_F];
__device__ bf16 g_w1h[4096*1024],   g_w1l[4096*1024];   // [n=4096][k=1024]
__device__ bf16 g_w2h[512*HK],      g_w2l[512*HK];      // [o=512][k=4160]
__device__ bf16 g_Hh[(size_t)B_ROWS*HK], g_Hl[(size_t)B_ROWS*HK];
__device__ float g_mix[B_ROWS*NLEAF];

// ---------------- helpers ----------------
__device__ __forceinline__ void bsplit(float v, bf16 &h, bf16 &l){
    h = __float2bfloat16(v);
    l = __float2bfloat16(v - __bfloat162float(h));
}
__device__ __forceinline__ uint32_t s2u(const void* p){
    uint32_t a;
    asm("{ .reg .u64 t; cvta.to.shared.u64 t, %1; cvt.u32.u64 %0, t; }" : "=r"(a) : "l"(p));
    return a;
}
__device__ __forceinline__ void cpasync16(uint32_t dst, const void* src){
    asm volatile("cp.async.cg.shared.global [%0], [%1], 16;" :: "r"(dst), "l"(src) : "memory");
}
__device__ __forceinline__ void cp_commit(){ asm volatile("cp.async.commit_group;" ::: "memory"); }
__device__ __forceinline__ void ldsm4(uint32_t* r, uint32_t a){
    asm volatile("ldmatrix.sync.aligned.m8n8.x4.shared.b16 {%0,%1,%2,%3}, [%4];"
        : "=r"(r[0]), "=r"(r[1]), "=r"(r[2]), "=r"(r[3]) : "r"(a));
}
__device__ __forceinline__ void mma16816(float* c, const uint32_t* a, uint32_t b0, uint32_t b1){
    asm volatile("mma.sync.aligned.m16n8k16.row.col.f32.bf16.bf16.f32 "
        "{%0,%1,%2,%3}, {%4,%5,%6,%7}, {%8,%9}, {%0,%1,%2,%3};"
        : "+f"(c[0]), "+f"(c[1]), "+f"(c[2]), "+f"(c[3])
        : "r"(a[0]), "r"(a[1]), "r"(a[2]), "r"(a[3]), "r"(b0), "r"(b1));
}

// =====================================================================
// Conversion kernels: fp32 -> (hi,lo) bf16 split (+transposes for B operands)
// =====================================================================
__global__ __launch_bounds__(256) void convx_kernel(const float* __restrict__ x){
    int i = blockIdx.x*256 + threadIdx.x;
    float4 v = ((const float4*)x)[i];
    __align__(8) bf16 h[4], l[4];
    bsplit(v.x,h[0],l[0]); bsplit(v.y,h[1],l[1]); bsplit(v.z,h[2],l[2]); bsplit(v.w,h[3],l[3]);
    *(ull*)&g_xh[(size_t)i*4] = *(ull*)h;
    *(ull*)&g_xl[(size_t)i*4] = *(ull*)l;
}

__global__ __launch_bounds__(256) void convw1_kernel(const float* __restrict__ w1){
    __shared__ float s[64][65];
    const int kc = blockIdx.x, l = blockIdx.y, tid = threadIdx.x;
    const float* src = w1 + ((size_t)l*1024 + kc*64)*64;
    for (int u = tid; u < 4096; u += 256) s[u>>6][u&63] = src[u];
    __syncthreads();
    const int w = tid>>2, i0 = (tid&3)*16;
    __align__(16) bf16 hh[16], ll[16];
#pragma unroll
    for (int i=0;i<16;i++) bsplit(s[i0+i][w], hh[i], ll[i]);
    size_t off = (size_t)(l*64+w)*1024 + kc*64 + i0;
    *(uint4*)&g_w1h[off]   = ((uint4*)hh)[0]; *(uint4*)&g_w1h[off+8] = ((uint4*)hh)[1];
    *(uint4*)&g_w1l[off]   = ((uint4*)ll)[0]; *(uint4*)&g_w1l[off+8] = ((uint4*)ll)[1];
}

__global__ __launch_bounds__(256) void convw2_kernel(const float* __restrict__ w2){
    __shared__ float s[64][65];
    const int ot = blockIdx.x, rt = blockIdx.y, tid = threadIdx.x;
    for (int u = tid; u < 4096; u += 256)
        s[u>>6][u&63] = w2[(size_t)(rt*64 + (u>>6))*512 + ot*64 + (u&63)];
    __syncthreads();
    const int o = tid>>2, i0 = (tid&3)*16;
    __align__(16) bf16 hh[16], ll[16];
#pragma unroll
    for (int i=0;i<16;i++) bsplit(s[i0+i][o], hh[i], ll[i]);
    size_t off = (size_t)(ot*64+o)*HK + rt*64 + i0;
    *(uint4*)&g_w2h[off]   = ((uint4*)hh)[0]; *(uint4*)&g_w2h[off+8] = ((uint4*)hh)[1];
    *(uint4*)&g_w2l[off]   = ((uint4*)ll)[0]; *(uint4*)&g_w2l[off+8] = ((uint4*)ll)[1];
}

__global__ __launch_bounds__(256) void convtail_kernel(const float* __restrict__ b2){
    __shared__ float s[64][65];
    const int ot = blockIdx.x, tid = threadIdx.x;
    for (int u = tid; u < 4096; u += 256)
        s[u>>6][u&63] = b2[(size_t)(u>>6)*512 + ot*64 + (u&63)];
    __syncthreads();
    const int o = tid>>2, j0 = (tid&3)*16;
    __align__(16) bf16 hh[16], ll[16];
#pragma unroll
    for (int i=0;i<16;i++) bsplit(s[j0+i][o], hh[i], ll[i]);
    size_t off = (size_t)(ot*64+o)*HK + 4096 + j0;
    *(uint4*)&g_w2h[off]   = ((uint4*)hh)[0]; *(uint4*)&g_w2h[off+8] = ((uint4*)hh)[1];
    *(uint4*)&g_w2l[off]   = ((uint4*)ll)[0]; *(uint4*)&g_w2l[off+8] = ((uint4*)ll)[1];
}

// =====================================================================
// Routing tree: 8 batch rows/block. Writes g_mix + hi/lo mixture tail of H.
// =====================================================================
__global__ __launch_bounds__(256) void mix_kernel(
    const float* __restrict__ x, const float* __restrict__ nw, const float* __restrict__ nb)
{
    __shared__ float xs[8*1024];
    __shared__ float lg[8][64];
    const int tid = threadIdx.x, warp = tid>>5, lane = tid&31;
    const int b0 = blockIdx.x * 8;

    for (int u = tid; u < 2048; u += 256)
        ((float4*)xs)[u] = ((const float4*)(x + (size_t)b0*IN_F))[u];
    __syncthreads();

    {
        float acc[8][8];
#pragma unroll
        for (int t=0;t<8;t++)
#pragma unroll
            for (int r=0;r<8;r++) acc[t][r] = 0.f;
        const float* wp[8];
#pragma unroll
        for (int t=0;t<8;t++){
            int nn = warp + 8*t;
            wp[t] = nw + (size_t)((nn < 63) ? nn : 0)*IN_F;
        }
        for (int j = 0; j < 32; ++j){
            const int o = lane + 32*j;
            float xv[8];
#pragma unroll
            for (int r=0;r<8;r++) xv[r] = xs[r*1024 + o];
#pragma unroll
            for (int t=0;t<8;t++){
                float wv = wp[t][o];
#pragma unroll
                for (int r=0;r<8;r++) acc[t][r] += xv[r]*wv;
            }
        }
#pragma unroll
        for (int t=0;t<8;t++){
            int nn = warp + 8*t;
#pragma unroll
            for (int r=0;r<8;r++){
                float s = acc[t][r];
#pragma unroll
                for (int o=16;o>0;o>>=1) s += __shfl_xor_sync(0xffffffffu, s, o);
                if (lane==0 && nn<63) lg[r][nn] = s + nb[nn];
            }
        }
    }
    __syncthreads();

#pragma unroll
    for (int p=0;p<2;p++){
        const int idx = tid + 256*p;
        const int r = idx>>6, l = idx&63;
        float m = 1.f;
#pragma unroll
        for (int d=0; d<6; ++d){
            int nidx = (1<<d) - 1 + (l >> (6-d));
            float sg = 1.f/(1.f + expf(-lg[r][nidx]));
            m *= ((l >> (5-d)) & 1) ? sg : (1.f - sg);
        }
        g_mix[(size_t)(b0+r)*NLEAF + l] = m;
        bf16 h, lo; bsplit(m, h, lo);
        g_Hh[(size_t)(b0+r)*HK + 4096 + l] = h;
        g_Hl[(size_t)(b0+r)*HK + 4096 + l] = lo;
    }
}

// =====================================================================
// HMMA split-bf16 GEMM, fused passes, 512 threads (16 warps, 4 per SMSP).
// CTA tile 128x128, warp tile 32x32 (4m x 4n warps), BK=64, 3-stage pipeline.
// Per chunk: load Ah,Al,Bh,Bl once; accumulate Ah*Bh + Al*Bh + Ah*Bl.
// EPI 1: bias+relu+mix -> Hh/Hl bf16.   EPI 2: plain fp32 store.
// =====================================================================
template<int KTOT, int EPI>
__global__ __launch_bounds__(512,1) void gemm_mma(const float* __restrict__ bias,
                                                  float* __restrict__ outp)
{
    extern __shared__ __align__(1024) char dsm[];
    const uint32_t smem0 = s2u(dsm);

    const int tid = threadIdx.x, wid = tid>>5, lane = tid&31;
    const int row0 = blockIdx.y*128, col0 = blockIdx.x*128;

    const int wm = wid>>2, wn = wid&3;          // 4 x 4 warp grid
    const int m0 = wm*32, n0 = wn*32;

    const bf16 *Ah, *Al, *Bh, *Bl;
    if (EPI==1){ Ah=g_xh; Al=g_xl; Bh=g_w1h; Bl=g_w1l; }
    else       { Ah=g_Hh; Al=g_Hl; Bh=g_w2h; Bl=g_w2l; }
    const int TOT = KTOT/64;

    // ---- cp.async mapping: 512 threads, each thread 32B (2x16B) per 16KB tile ----
    const int lr = tid>>2;                      // tile row 0..127
    const int lc = (tid&3)*32;                  // byte col 0/32/64/96
    const uint32_t dstrel = lr*128 + (((lr&7)<<4) ^ lc);
    const int lce = lc>>1;                      // element offset
    const bf16* Arow_h = Ah + (size_t)(row0+lr)*KTOT + lce;
    const bf16* Arow_l = Al + (size_t)(row0+lr)*KTOT + lce;
    const bf16* Brow_h = Bh + (size_t)(col0+lr)*KTOT + lce;
    const bf16* Brow_l = Bl + (size_t)(col0+lr)*KTOT + lce;

    // ---- ldmatrix per-lane relative offsets (SW128 folded in) ----
    uint32_t relA[2], relB[2];
    {
        const int mat = lane>>3, r = lane&7;
        const int cfA = (mat>>1)*16;
#pragma unroll
        for (int mi=0; mi<2; ++mi){
            int row = m0 + mi*16 + (mat&1)*8 + r;
            relA[mi] = row*128 + ((((row&7)<<4) ^ cfA));
        }
        const int cfB = (mat&1)*16;
#pragma unroll
        for (int j=0; j<2; ++j){
            int row = n0 + j*16 + (mat>>1)*8 + r;
            relB[j] = row*128 + ((((row&7)<<4) ^ cfB));
        }
    }

    float acc[2][4][4];
#pragma unroll
    for (int mi=0;mi<2;mi++)
#pragma unroll
        for (int ni=0;ni<4;ni++)
#pragma unroll
            for (int q=0;q<4;q++) acc[mi][ni][q] = 0.f;

    // ---- issue chunk c into stage s: 4 tiles (Ah | Al | Bh | Bl) ----
    auto issue = [&](int c, int s){
        const int kk = c*64;
        const uint32_t d0 = smem0 + s*STAGE_BYTES + dstrel;
        const bf16* pah = Arow_h + kk;
        const bf16* pal = Arow_l + kk;
        const bf16* pbh = Brow_h + kk;
        const bf16* pbl = Brow_l + kk;
#pragma unroll
        for (int i=0;i<2;i++) cpasync16( d0           ^ (i*16), pah + i*8);
#pragma unroll
        for (int i=0;i<2;i++) cpasync16((d0 + 16384) ^ (i*16), pal + i*8);
#pragma unroll
        for (int i=0;i<2;i++) cpasync16((d0 + 32768) ^ (i*16), pbh + i*8);
#pragma unroll
        for (int i=0;i<2;i++) cpasync16((d0 + 49152) ^ (i*16), pbl + i*8);
        cp_commit();
    };

    issue(0, 0);
    issue(1, 1);

    for (int c = 0; c < TOT; ++c){
        if (c == TOT-1) asm volatile("cp.async.wait_group 0;" ::: "memory");
        else            asm volatile("cp.async.wait_group 1;" ::: "memory");
        __syncthreads();
        if (c+2 < TOT) issue(c+2, (c+2)%3);

        const uint32_t sAh = smem0 + (c%3)*STAGE_BYTES;
        const uint32_t sAl = sAh + 16384;
        const uint32_t sBh = sAh + 32768;
        const uint32_t sBl = sAh + 49152;
#pragma unroll
        for (int ks=0; ks<4; ++ks){
            const uint32_t kx = ks*32;
            uint32_t ah[2][4], al[2][4], bh[2][4], bl[2][4];
#pragma unroll
            for (int mi=0;mi<2;mi++) ldsm4(ah[mi], sAh + (relA[mi] ^ kx));
#pragma unroll
            for (int j=0;j<2;j++)    ldsm4(bh[j], sBh + (relB[j] ^ kx));
#pragma unroll
            for (int mi=0;mi<2;mi++) ldsm4(al[mi], sAl + (relA[mi] ^ kx));
#pragma unroll
            for (int j=0;j<2;j++)    ldsm4(bl[j], sBl + (relB[j] ^ kx));
            // pass0: Ah*Bh
#pragma unroll
            for (int mi=0;mi<2;mi++)
#pragma unroll
                for (int ni=0;ni<4;ni++)
                    mma16816(acc[mi][ni], ah[mi], bh[ni>>1][(ni&1)*2], bh[ni>>1][(ni&1)*2+1]);
            // pass1: Al*Bh
#pragma unroll
            for (int mi=0;mi<2;mi++)
#pragma unroll
                for (int ni=0;ni<4;ni++)
                    mma16816(acc[mi][ni], al[mi], bh[ni>>1][(ni&1)*2], bh[ni>>1][(ni&1)*2+1]);
            // pass2: Ah*Bl
#pragma unroll
            for (int mi=0;mi<2;mi++)
#pragma unroll
                for (int ni=0;ni<4;ni++)
                    mma16816(acc[mi][ni], ah[mi], bl[ni>>1][(ni&1)*2], bl[ni>>1][(ni&1)*2+1]);
        }
    }

    // ---- epilogue ----
    const int g = lane>>2, tig = lane&3;
    const int leaf = (col0 + n0) >> 6;      // 32-col warp tile never crosses a leaf
#pragma unroll
    for (int mi=0; mi<2; ++mi){
        const int ra = row0 + m0 + mi*16 + g;
        float mx0 = 0.f, mx1 = 0.f;
        if (EPI == 1){
            mx0 = g_mix[(size_t)ra*NLEAF + leaf];
            mx1 = g_mix[(size_t)(ra+8)*NLEAF + leaf];
        }
#pragma unroll
        for (int ni=0; ni<4; ++ni){
            const int col = col0 + n0 + ni*8 + tig*2;
            if (EPI == 1){
                const float b0v = bias[col], b1v = bias[col+1];
                float v00 = fmaxf(acc[mi][ni][0] + b0v, 0.f) * mx0;
                float v01 = fmaxf(acc[mi][ni][1] + b1v, 0.f) * mx0;
                float v10 = fmaxf(acc[mi][ni][2] + b0v, 0.f) * mx1;
                float v11 = fmaxf(acc[mi][ni][3] + b1v, 0.f) * mx1;
                __align__(4) bf16 h0[2], l0[2], h1[2], l1[2];
                bsplit(v00, h0[0], l0[0]); bsplit(v01, h0[1], l0[1]);
                bsplit(v10, h1[0], l1[0]); bsplit(v11, h1[1], l1[1]);
                *(uint32_t*)&g_Hh[(size_t)ra*HK + col]     = *(uint32_t*)h0;
                *(uint32_t*)&g_Hl[(size_t)ra*HK + col]     = *(uint32_t*)l0;
                *(uint32_t*)&g_Hh[(size_t)(ra+8)*HK + col] = *(uint32_t*)h1;
                *(uint32_t*)&g_Hl[(size_t)(ra+8)*HK + col] = *(uint32_t*)l1;
            } else {
                *(float2*)&outp[(size_t)ra*OUT_F + col]     = make_float2(acc[mi][ni][0], acc[mi][ni][1]);
                *(float2*)&outp[(size_t)(ra+8)*OUT_F + col] = make_float2(acc[mi][ni][2], acc[mi][ni][3]);
            }
        }
    }
}

// =====================================================================
extern "C" void kernel_launch(void* const* d_in, const int* in_sizes, int n_in,
                              void* d_out, int out_size) {
    const float* x   = (const float*)d_in[0];   // [4096,1024]
    const float* nw  = (const float*)d_in[1];   // [63,1024]
    const float* nb  = (const float*)d_in[2];   // [63,1]
    const float* w1s = (const float*)d_in[3];   // [64,1024,64]
    const float* b1s = (const float*)d_in[4];   // [64,64] flat = H column
    const float* w2s = (const float*)d_in[5];   // [64,64,512] flat = [4096,512]
    const float* b2s = (const float*)d_in[6];   // [64,512]
    float* out = (float*)d_out;                 // [4096,512]

    cudaFuncSetAttribute(gemm_mma<IN_F,1>, cudaFuncAttributeMaxDynamicSharedMemorySize, SMEMSZ);
    cudaFuncSetAttribute(gemm_mma<HK,2>,   cudaFuncAttributeMaxDynamicSharedMemorySize, SMEMSZ);

    convx_kernel   <<<4096, 256>>>(x);
    convw1_kernel  <<<dim3(16,64), 256>>>(w1s);
    convw2_kernel  <<<dim3(8,64),  256>>>(w2s);
    convtail_kernel<<<8, 256>>>(b2s);
    mix_kernel     <<<512, 256>>>(x, nw, nb);

    gemm_mma<IN_F,1><<<dim3(32,32), 512, SMEMSZ>>>(b1s, nullptr);   // H = relu(x@W1+b1)*mix
    gemm_mma<HK,2>  <<<dim3(4,32),  512, SMEMSZ>>>(nullptr, out);   // out = Hm@W2 + mix@b2
}